// round 6
// baseline (speedup 1.0000x reference)
#include <cuda_runtime.h>
#include <cstdint>

// Problem constants (fixed by the dataset)
#define B_    2
#define NH_   8
#define N_    4096
#define D_    64
#define K2_   49
#define V_F4  784          // D*K2/4
#define THREADS 96         // warps 0-1: consumers (64 thr), warp 2: producer
#define ROWS  16           // rows per CTA (16 | 4096 so h constant per CTA)
#define STAGES 3

__device__ __forceinline__ uint32_t smem_u32(const void* p) {
    return (uint32_t)__cvta_generic_to_shared(p);
}
__device__ __forceinline__ void cp16(uint32_t dst, const void* src) {
    // .cg => bypass L1; v_local is pure streaming
    asm volatile("cp.async.cg.shared.global [%0], [%1], 16;\n" :: "r"(dst), "l"(src));
}
__device__ __forceinline__ void cp4(uint32_t dst, const void* src) {
    asm volatile("cp.async.ca.shared.global [%0], [%1], 4;\n" :: "r"(dst), "l"(src));
}
__device__ __forceinline__ void mbar_init(uint32_t a, uint32_t cnt) {
    asm volatile("mbarrier.init.shared.b64 [%0], %1;" :: "r"(a), "r"(cnt) : "memory");
}
__device__ __forceinline__ void mbar_arrive(uint32_t a) {
    asm volatile("mbarrier.arrive.shared.b64 _, [%0];" :: "r"(a) : "memory");
}
// this thread's outstanding cp.asyncs arrive on the mbarrier when they complete
__device__ __forceinline__ void cp_arrive_on(uint32_t a) {
    asm volatile("cp.async.mbarrier.arrive.noinc.shared.b64 [%0];" :: "r"(a) : "memory");
}
__device__ __forceinline__ void mbar_wait(uint32_t a, uint32_t parity) {
    asm volatile(
        "{\n\t.reg .pred P;\n\t"
        "WL_%=:\n\t"
        "mbarrier.try_wait.parity.acquire.cta.shared::cta.b64 P, [%0], %1, 0x989680;\n\t"
        "@P bra.uni WD_%=;\n\t"
        "bra.uni WL_%=;\n\t"
        "WD_%=:\n\t}"
        :: "r"(a), "r"(parity) : "memory");
}

struct __align__(16) Stage {
    float4 v[V_F4];        // 12544 B
    float  q[D_];          // 256 B
    float  al[K2_];        // 196 B
    float  b[K2_];         // 196 B
    float  pad[2];         // sizeof = 13200 (16B multiple)
};

__global__ __launch_bounds__(THREADS)
void sw_attention_av_ws(const float* __restrict__ q_norm,      // [B,NH,N,D]
                        const float* __restrict__ attn_local,  // [B,NH,N,K2]
                        const float* __restrict__ v_local,     // [B,NH,N,D,K2]
                        const float* __restrict__ tokens,      // [NH,D,K2]
                        const float* __restrict__ bias,        // [NH,N,K2]
                        float* __restrict__ out)               // [B,NH,N,D]
{
    __shared__ Stage    st[STAGES];
    __shared__ uint64_t full_mb[STAGES];
    __shared__ uint64_t empty_mb[STAGES];
    __shared__ float    s_attn[2][K2_];

    const int t    = threadIdx.x;
    const int row0 = blockIdx.x * ROWS;
    const int h    = (row0 >> 12) & (NH_ - 1);

    if (t == 0) {
#pragma unroll
        for (int s = 0; s < STAGES; s++) {
            mbar_init(smem_u32(&full_mb[s]),  32);   // 32 producer lanes
            mbar_init(smem_u32(&empty_mb[s]), 64);   // 64 consumer threads
        }
    }
    __syncthreads();   // only block-wide sync; producer/consumers diverge after

    if (t >= 64) {
        // ================= PRODUCER (warp 2) =================
        const int l = t - 64;                        // lane 0..31
        int ps = 0, pphase = 1;                      // phase 1: first empty-wait passes
        for (int r = 0; r < ROWS; r++) {
            mbar_wait(smem_u32(&empty_mb[ps]), (uint32_t)pphase);

            const int row = row0 + r;
            const float4* vrow = reinterpret_cast<const float4*>(v_local)
                                 + (size_t)row * V_F4;
            uint32_t vdst = smem_u32(st[ps].v);
#pragma unroll
            for (int i = 0; i < 24; i++)             // 24*32 = 768
                cp16(vdst + (uint32_t)(l + 32 * i) * 16u, vrow + l + 32 * i);
            if (l < 16)                              // 784-768 leftover
                cp16(vdst + (uint32_t)(768 + l) * 16u, vrow + 768 + l);

            if (l < 16)                              // q: 64 floats = 16 float4
                cp16(smem_u32(st[ps].q) + (uint32_t)l * 16u,
                     reinterpret_cast<const float4*>(q_norm + (size_t)row * D_) + l);

            {
                const int n = row & (N_ - 1);
                const float* alp = attn_local + (size_t)row * K2_;
                const float* bp  = bias + ((size_t)h * N_ + n) * K2_;
                cp4(smem_u32(st[ps].al) + (uint32_t)l * 4u, alp + l);
                cp4(smem_u32(st[ps].b)  + (uint32_t)l * 4u, bp  + l);
                if (l < K2_ - 32) {
                    cp4(smem_u32(st[ps].al) + (uint32_t)(l + 32) * 4u, alp + l + 32);
                    cp4(smem_u32(st[ps].b)  + (uint32_t)(l + 32) * 4u, bp  + l + 32);
                }
            }
            cp_arrive_on(smem_u32(&full_mb[ps]));    // arrive when these cps land

            if (++ps == STAGES) { ps = 0; pphase ^= 1; }
        }
    } else {
        // ================= CONSUMERS (warps 0-1, 64 threads) =================
        const float* tok_h = tokens + h * (D_ * K2_);
        int cs = 0, cphase = 0;
        for (int r = 0; r < ROWS; r++) {
            mbar_wait(smem_u32(&full_mb[cs]), (uint32_t)cphase);
            const Stage& S = st[cs];
            float* attn_buf = s_attn[r & 1];

            // ---- phase 1: attn[k] = q . tokens[:,k] + bias + attn_local
            if (t < K2_) {
                const float* tk = tok_h + t;
                float a0 = 0.f, a1 = 0.f;
#pragma unroll
                for (int d = 0; d < D_; d += 2) {
                    a0 = fmaf(S.q[d + 0], __ldg(tk + (d + 0) * K2_), a0);
                    a1 = fmaf(S.q[d + 1], __ldg(tk + (d + 1) * K2_), a1);
                }
                attn_buf[t] = a0 + a1 + S.b[t] + S.al[t];
            }
            asm volatile("bar.sync 1, 64;" ::: "memory");   // consumers only

            // ---- phase 2: out[d] = sum_k attn[k] * v[d,k]  (stride-49: conflict-free)
            {
                const float* vd = reinterpret_cast<const float*>(S.v) + t * K2_;
                float acc0 = 0.f, acc1 = 0.f;
#pragma unroll
                for (int k = 0; k < 48; k += 2) {
                    acc0 = fmaf(attn_buf[k + 0], vd[k + 0], acc0);
                    acc1 = fmaf(attn_buf[k + 1], vd[k + 1], acc1);
                }
                acc0 = fmaf(attn_buf[48], vd[48], acc0);
                out[(size_t)(row0 + r) * D_ + t] = acc0 + acc1;
            }

            mbar_arrive(smem_u32(&empty_mb[cs]));    // stage free for producer

            if (++cs == STAGES) { cs = 0; cphase ^= 1; }
        }
    }
}

extern "C" void kernel_launch(void* const* d_in, const int* in_sizes, int n_in,
                              void* d_out, int out_size)
{
    const float* q_norm     = (const float*)d_in[0];
    const float* attn_local = (const float*)d_in[1];
    const float* v_local    = (const float*)d_in[2];
    const float* tokens     = (const float*)d_in[3];
    const float* bias       = (const float*)d_in[4];
    float* out = (float*)d_out;

    const int blocks = (B_ * NH_ * N_) / ROWS;   // 4096
    sw_attention_av_ws<<<blocks, THREADS>>>(q_norm, attn_local, v_local,
                                            tokens, bias, out);
}

// round 7
// speedup vs baseline: 1.0205x; 1.0205x over previous
#include <cuda_runtime.h>
#include <cstdint>

#define B_    2
#define NH_   8
#define N_    4096
#define D_    64
#define K2_   49
#define V_F4  784          // D*K2/4
#define THREADS 128
#define ROWS  8            // rows per CTA in kernel2
#define TN    128          // rows per CTA in kernel1

// 12.8 MB scratch for precomputed attention logits  [B,NH,N,K2]
__device__ float g_attn[(size_t)B_ * NH_ * N_ * K2_];

// ---------------------------------------------------------------------------
// helpers
// ---------------------------------------------------------------------------
__device__ __forceinline__ uint32_t smem_u32(const void* p) {
    return (uint32_t)__cvta_generic_to_shared(p);
}
__device__ __forceinline__ void cp16(uint32_t dst, const void* src) {
    asm volatile("cp.async.cg.shared.global [%0], [%1], 16;\n" :: "r"(dst), "l"(src));
}
__device__ __forceinline__ void cp4(uint32_t dst, const void* src) {
    asm volatile("cp.async.ca.shared.global [%0], [%1], 4;\n" :: "r"(dst), "l"(src));
}
__device__ __forceinline__ void cp_commit() {
    asm volatile("cp.async.commit_group;\n" ::: "memory");
}
template <int NPend>
__device__ __forceinline__ void cp_wait() {
    asm volatile("cp.async.wait_group %0;\n" :: "n"(NPend) : "memory");
}

// ---------------------------------------------------------------------------
// Kernel 1: attn[row][k] = sum_d q[row][d]*tok[h][d][k] + bias + attn_local
// One CTA = 128 consecutive rows (same head). FMA-bound, tokens in smem.
// ---------------------------------------------------------------------------
#define TOK_PITCH 52       // 49 padded to 16B multiple (52*4=208B) for LDS.128

__global__ __launch_bounds__(TN)
void attn_gemv_kernel(const float* __restrict__ q_norm,      // [B,NH,N,D]
                      const float* __restrict__ attn_local,  // [B,NH,N,K2]
                      const float* __restrict__ tokens,      // [NH,D,K2]
                      const float* __restrict__ bias)        // [NH,N,K2]
{
    __shared__ float s_tok[D_ * TOK_PITCH];   // 13312 B
    __shared__ float s_out[TN * K2_];         // 25088 B

    const int t    = threadIdx.x;
    const int row0 = blockIdx.x * TN;
    const int h    = (row0 >> 12) & (NH_ - 1);

    // tokens[h] -> smem (one-time; broadcast-read afterwards)
    {
        const float* tk = tokens + h * (D_ * K2_);
        for (int i = t; i < D_ * K2_; i += TN)
            s_tok[(i / K2_) * TOK_PITCH + (i % K2_)] = tk[i];
    }
    __syncthreads();

    // each thread: one row, 49 accumulators (12 x float4 + 1)
    const int row = row0 + t;
    const float4* qr = reinterpret_cast<const float4*>(q_norm + (size_t)row * D_);

    float4 acc[12];
    float  acc48 = 0.f;
#pragma unroll
    for (int i = 0; i < 12; i++) acc[i] = make_float4(0.f, 0.f, 0.f, 0.f);

#pragma unroll
    for (int c = 0; c < 16; c++) {
        const float4 qv = __ldg(qr + c);
        const float qs[4] = {qv.x, qv.y, qv.z, qv.w};
#pragma unroll
        for (int j = 0; j < 4; j++) {
            const int d = 4 * c + j;
            const float qd = qs[j];
            const float4* trow = reinterpret_cast<const float4*>(s_tok + d * TOK_PITCH);
#pragma unroll
            for (int i = 0; i < 12; i++) {       // broadcast LDS.128
                const float4 tv = trow[i];
                acc[i].x = fmaf(qd, tv.x, acc[i].x);
                acc[i].y = fmaf(qd, tv.y, acc[i].y);
                acc[i].z = fmaf(qd, tv.z, acc[i].z);
                acc[i].w = fmaf(qd, tv.w, acc[i].w);
            }
            acc48 = fmaf(qd, s_tok[d * TOK_PITCH + 48], acc48);
        }
    }

    // stage into smem as [row][k] (flat == linear order of the scratch block)
    float* so = s_out + t * K2_;
#pragma unroll
    for (int i = 0; i < 12; i++) {
        so[4 * i + 0] = acc[i].x;
        so[4 * i + 1] = acc[i].y;
        so[4 * i + 2] = acc[i].z;
        so[4 * i + 3] = acc[i].w;
    }
    so[48] = acc48;
    __syncthreads();

    // coalesced epilogue: += attn_local + bias (both contiguous for this CTA)
    const int n0 = row0 & (N_ - 1);
    const float* al0 = attn_local + (size_t)row0 * K2_;
    const float* b0  = bias + ((size_t)h * N_ + n0) * K2_;
    float* dst = g_attn + (size_t)row0 * K2_;
    for (int i = t; i < TN * K2_; i += TN)
        dst[i] = s_out[i] + __ldg(al0 + i) + __ldg(b0 + i);
}

// ---------------------------------------------------------------------------
// Kernel 2: pure stream  out[row][d] = sum_k attn[row][k] * v[row][d][k]
// ---------------------------------------------------------------------------
struct __align__(16) Stage {
    float4 v[V_F4];        // 12544 B
    float  a[K2_];         // 196 B
    float  pad[3];         // sizeof = 12752 (16B multiple)
};

__global__ __launch_bounds__(THREADS)
void av_stream_kernel(const float* __restrict__ v_local,     // [B,NH,N,D,K2]
                      float* __restrict__ out)               // [B,NH,N,D]
{
    __shared__ Stage st[2];

    const int t    = threadIdx.x;
    const int row0 = blockIdx.x * ROWS;

    auto prefetch = [&](int s, int row) {
        const float4* vrow = reinterpret_cast<const float4*>(v_local) + (size_t)row * V_F4;
        uint32_t vdst = smem_u32(st[s].v);
#pragma unroll
        for (int i = 0; i < 6; i++)
            cp16(vdst + (uint32_t)(t + THREADS * i) * 16u, vrow + t + THREADS * i);
        if (t < V_F4 - 6 * THREADS)                   // 16 leftover float4
            cp16(vdst + (uint32_t)(t + 6 * THREADS) * 16u, vrow + t + 6 * THREADS);

        if (t < K2_)
            cp4(smem_u32(st[s].a) + (uint32_t)t * 4u, g_attn + (size_t)row * K2_ + t);
        cp_commit();
    };

    prefetch(0, row0);

    for (int r = 0; r < ROWS; r++) {
        if (r + 1 < ROWS) {
            prefetch((r + 1) & 1, row0 + r + 1);
            cp_wait<1>();
        } else {
            cp_wait<0>();
        }
        __syncthreads();                              // stage r&1 ready

        const Stage& S = st[r & 1];

        if (t < D_) {
            const float* vd = reinterpret_cast<const float*>(S.v) + t * K2_;
            float acc0 = 0.f, acc1 = 0.f;
#pragma unroll
            for (int k = 0; k < 48; k += 2) {
                acc0 = fmaf(S.a[k + 0], vd[k + 0], acc0);
                acc1 = fmaf(S.a[k + 1], vd[k + 1], acc1);
            }
            acc0 = fmaf(S.a[48], vd[48], acc0);
            out[(size_t)(row0 + r) * D_ + t] = acc0 + acc1;
        }

        __syncthreads();                              // readers done before overwrite
    }
}

// ---------------------------------------------------------------------------
extern "C" void kernel_launch(void* const* d_in, const int* in_sizes, int n_in,
                              void* d_out, int out_size)
{
    const float* q_norm     = (const float*)d_in[0];
    const float* attn_local = (const float*)d_in[1];
    const float* v_local    = (const float*)d_in[2];
    const float* tokens     = (const float*)d_in[3];
    const float* bias       = (const float*)d_in[4];
    float* out = (float*)d_out;

    attn_gemv_kernel<<<(B_ * NH_ * N_) / TN, TN>>>(q_norm, attn_local, tokens, bias);
    av_stream_kernel<<<(B_ * NH_ * N_) / ROWS, THREADS>>>(v_local, out);
}